// round 9
// baseline (speedup 1.0000x reference)
#include <cuda_runtime.h>

// R7: break the smem-crossbar wall. The loop loads k/v (32B) once per s per
// LANE and reuses it for 4 queries (lane owns tokens 4a..4a+3; half-warp per
// batch). Lane-bytes/pair: 32B -> ~8.4B. Scores packed query-pairwise with
// fma.rn.f32x2; causal tail = 3 unrolled iters with compile-time -200 biases.
// Divergent per-lane trip counts let light lanes stop loading (saves bytes).
// Precompute kernel builds 640-entry qtab/kvtab (AoS, L1-resident).

#define TT 64
#define BPB 8                      // batches per block
#define NTH 128                    // 4 warps; warp = 2 batches
#define VOCAB 10

typedef unsigned long long u64;

__device__ float4 g_qtab[VOCAB * TT];          // Q pre-scaled by 0.5*log2e
__device__ float4 g_kvtab[VOCAB * TT * 2];     // [e][0]=K, [e][1]=V
__device__ float2 g_tok[VOCAB];
__device__ float  g_pe[TT];

__device__ __forceinline__ float ex2f(float x) {
    float y; asm("ex2.approx.ftz.f32 %0, %1;" : "=f"(y) : "f"(x)); return y;
}
__device__ __forceinline__ float rcpf(float x) {
    float y; asm("rcp.approx.ftz.f32 %0, %1;" : "=f"(y) : "f"(x)); return y;
}
__device__ __forceinline__ u64 pack2(float lo, float hi) {
    u64 r; asm("mov.b64 %0, {%1, %2};" : "=l"(r) : "f"(lo), "f"(hi)); return r;
}
__device__ __forceinline__ void unpack2(u64 v, float& lo, float& hi) {
    asm("mov.b64 {%0, %1}, %2;" : "=f"(lo), "=f"(hi) : "l"(v));
}
__device__ __forceinline__ u64 fma2(u64 a, u64 b, u64 c) {
    u64 d; asm("fma.rn.f32x2 %0, %1, %2, %3;" : "=l"(d) : "l"(a), "l"(b), "l"(c)); return d;
}
__device__ __forceinline__ u64 add2(u64 a, u64 b) {
    u64 d; asm("add.rn.f32x2 %0, %1, %2;" : "=l"(d) : "l"(a), "l"(b)); return d;
}

// ---------------- kernel 1: 640-entry tables ----------------
__global__ void precompute_kernel(
    const float* __restrict__ pA,
    const float* __restrict__ pS,
    const float* __restrict__ pD,
    const float* __restrict__ w_ln1,
    const float* __restrict__ w_qn,
    const float* __restrict__ Wq,
    const float* __restrict__ Wk)
{
    const int dig = blockIdx.x;    // 0..9
    const int t   = threadIdx.x;   // 0..63

    const float A = pA[0], ast = pS[0], astr = pD[0];
    float sa, ca;
    sincosf(ast + (float)dig * astr, &sa, &ca);
    const float x0 = A * ca;
    const float x1 = A * sa;
    const float x2 = sinf((float)t * 1.0e-4f);

    if (t == 0)   g_tok[dig] = make_float2(x0, x1);
    if (dig == 0) g_pe[t] = x2;

    const float r = rsqrtf((x0*x0 + x1*x1 + x2*x2) * (1.0f/3.0f) + 1e-6f);
    const float h0 = x0 * r * w_ln1[0];
    const float h1 = x1 * r * w_ln1[1];
    const float h2 = x2 * r * w_ln1[2];

    float qr[4], kv[4];
#pragma unroll
    for (int j = 0; j < 4; ++j) {
        qr[j] = h0 * Wq[j*3+0] + h1 * Wq[j*3+1] + h2 * Wq[j*3+2];
        kv[j] = h0 * Wk[j*3+0] + h1 * Wk[j*3+1] + h2 * Wk[j*3+2];
    }
    const float rq = rsqrtf((qr[0]*qr[0]+qr[1]*qr[1]+qr[2]*qr[2]+qr[3]*qr[3]) * 0.25f + 1e-6f);
    const float rk = rsqrtf((kv[0]*kv[0]+kv[1]*kv[1]+kv[2]*kv[2]+kv[3]*kv[3]) * 0.25f + 1e-6f);
    const float q0 = qr[0]*rq*w_qn[0], q1 = qr[1]*rq*w_qn[1];
    const float q2 = qr[2]*rq*w_qn[2], q3 = qr[3]*rq*w_qn[3];
    const float k0 = kv[0]*rk*w_qn[0], k1 = kv[1]*rk*w_qn[1];
    const float k2 = kv[2]*rk*w_qn[2], k3 = kv[3]*rk*w_qn[3];

    float s0, c0, s1, c1;
    sincosf((float)t, &s0, &c0);
    sincosf((float)t * 0.57735026918962576f, &s1, &c1);

    const float SC = 0.5f * 1.4426950408889634f;
    const int e = dig * TT + t;
    g_qtab[e] = make_float4((q0*c0 - q1*s0)*SC, (q0*s0 + q1*c0)*SC,
                            (q2*c1 - q3*s1)*SC, (q2*s1 + q3*c1)*SC);
    g_kvtab[2*e]     = make_float4(k0*c0 - k1*s0, k0*s0 + k1*c0,
                                   k2*c1 - k3*s1, k2*s1 + k3*c1);
    g_kvtab[2*e + 1] = make_float4(kv[0], kv[1], kv[2], kv[3]);
}

// wsm: [0..2] w_ln2, [3..5] w_lnf, [6..17] Wq, [18..23] Wg, [24..29] Wu, [30..35] Wd
__global__ __launch_bounds__(NTH)
void adder_main(
    const int* __restrict__ idx,
    const float* __restrict__ w_ln2,
    const float* __restrict__ w_lnf,
    const float* __restrict__ Wq,
    const float* __restrict__ Wg,
    const float* __restrict__ Wu,
    const float* __restrict__ Wd,
    float* __restrict__ out)
{
    __shared__ __align__(16) float4 smkv[BPB][TT][2];   // 16 KB
    __shared__ int   digs[BPB * TT];                    // 2 KB
    __shared__ float wsm[36];
    __shared__ float2 tok2[VOCAB];
    __shared__ float pe[TT];

    const int tid = threadIdx.x;

    if (tid < 36) {
        float v;
        if      (tid < 3)  v = w_ln2[tid];
        else if (tid < 6)  v = w_lnf[tid - 3];
        else if (tid < 18) v = Wq[tid - 6];
        else if (tid < 24) v = Wg[tid - 18];
        else if (tid < 30) v = Wu[tid - 24];
        else               v = Wd[tid - 30];
        wsm[tid] = v;
    }
    if (tid < VOCAB) tok2[tid] = g_tok[tid];
    if (tid < TT)    pe[tid]   = g_pe[tid];

    // ---- staging: 512 tokens, 4 per thread (coalesced idx reads) ----
#pragma unroll
    for (int j = 0; j < 4; ++j) {
        const int tau = tid + j * NTH;             // 0..511
        const int b = tau >> 6, t = tau & 63;
        const int dig = idx[(size_t)blockIdx.x * (BPB * TT) + tau];
        digs[tau] = dig;
        const int e = dig * TT + t;
        smkv[b][t][0] = g_kvtab[2*e];
        smkv[b][t][1] = g_kvtab[2*e + 1];
    }
    __syncthreads();

    // ---- attention: warp = 2 batches; lane = (half, a); queries 4a..4a+3 ----
    const int w    = tid >> 5;
    const int lane = tid & 31;
    const int half = lane >> 4;
    const int a    = lane & 15;
    const int b    = 2*w + half;

    // load Q for the 4 queries (gmem table, L1-hot)
    u64 QP0[4], QP1[4];                 // pair (q0,q1) and (q2,q3) per component
    {
        const int t0 = 4*a;
        const float4 qa = g_qtab[digs[b*TT + t0    ] * TT + t0    ];
        const float4 qb = g_qtab[digs[b*TT + t0 + 1] * TT + t0 + 1];
        const float4 qc = g_qtab[digs[b*TT + t0 + 2] * TT + t0 + 2];
        const float4 qd = g_qtab[digs[b*TT + t0 + 3] * TT + t0 + 3];
        QP0[0] = pack2(qa.x, qb.x); QP0[1] = pack2(qa.y, qb.y);
        QP0[2] = pack2(qa.z, qb.z); QP0[3] = pack2(qa.w, qb.w);
        QP1[0] = pack2(qc.x, qd.x); QP1[1] = pack2(qc.y, qd.y);
        QP1[2] = pack2(qc.z, qd.z); QP1[3] = pack2(qc.w, qd.w);
    }

    u64 sum0 = 0ULL, sum1 = 0ULL;
    u64 acc0[4] = {0,0,0,0}, acc1[4] = {0,0,0,0};

#define ATT_STEP(S, BIAS0, BIAS1)                                              \
    {                                                                          \
        const float4 kk = smkv[b][S][0];                                       \
        const float4 vv = smkv[b][S][1];                                       \
        const u64 kx = pack2(kk.x, kk.x), ky = pack2(kk.y, kk.y);              \
        const u64 kz = pack2(kk.z, kk.z), kw = pack2(kk.w, kk.w);              \
        const u64 sc0 = fma2(QP0[0], kx, fma2(QP0[1], ky,                      \
                        fma2(QP0[2], kz, fma2(QP0[3], kw, (BIAS0)))));         \
        const u64 sc1 = fma2(QP1[0], kx, fma2(QP1[1], ky,                      \
                        fma2(QP1[2], kz, fma2(QP1[3], kw, (BIAS1)))));         \
        float l0, h0f, l1, h1f;                                                \
        unpack2(sc0, l0, h0f); unpack2(sc1, l1, h1f);                          \
        const u64 p0 = pack2(ex2f(l0), ex2f(h0f));                             \
        const u64 p1 = pack2(ex2f(l1), ex2f(h1f));                             \
        sum0 = add2(sum0, p0); sum1 = add2(sum1, p1);                          \
        const u64 vx = pack2(vv.x, vv.x), vy = pack2(vv.y, vv.y);              \
        const u64 vz = pack2(vv.z, vv.z), vw = pack2(vv.w, vv.w);              \
        acc0[0] = fma2(p0, vx, acc0[0]); acc0[1] = fma2(p0, vy, acc0[1]);      \
        acc0[2] = fma2(p0, vz, acc0[2]); acc0[3] = fma2(p0, vw, acc0[3]);      \
        acc1[0] = fma2(p1, vx, acc1[0]); acc1[1] = fma2(p1, vy, acc1[1]);      \
        acc1[2] = fma2(p1, vz, acc1[2]); acc1[3] = fma2(p1, vw, acc1[3]);      \
    }

    const u64 Z = 0ULL;
    const int smain = 4*a;                    // all 4 queries active for s<=4a
#pragma unroll 4
    for (int s = 0; s <= smain; ++s) ATT_STEP(s, Z, Z)

    // causal tail: compile-time bias masks
    const u64 M10 = pack2(-200.0f,    0.0f);
    const u64 M11 = pack2(-200.0f, -200.0f);
    ATT_STEP(smain + 1, M10, Z)               // q0 off
    ATT_STEP(smain + 2, M11, Z)               // q0,q1 off
    ATT_STEP(smain + 3, M11, M10)             // q0,q1,q2 off
#undef ATT_STEP

    // ---- epilogue: 4 queries per lane ----
    float sA, sB;
    float oA[4], oB[4];

#pragma unroll
    for (int pair = 0; pair < 2; ++pair) {
        if (pair == 0) {
            unpack2(sum0, sA, sB);
            unpack2(acc0[0], oA[0], oB[0]); unpack2(acc0[1], oA[1], oB[1]);
            unpack2(acc0[2], oA[2], oB[2]); unpack2(acc0[3], oA[3], oB[3]);
        } else {
            unpack2(sum1, sA, sB);
            unpack2(acc1[0], oA[0], oB[0]); unpack2(acc1[1], oA[1], oB[1]);
            unpack2(acc1[2], oA[2], oB[2]); unpack2(acc1[3], oA[3], oB[3]);
        }
#pragma unroll
        for (int k = 0; k < 2; ++k) {
            const int t = 4*a + 2*pair + k;
            const float inv = rcpf(k ? sB : sA);
            const float o0 = (k ? oB[0] : oA[0]) * inv;
            const float o1 = (k ? oB[1] : oA[1]) * inv;
            const float o2 = (k ? oB[2] : oA[2]) * inv;
            const float o3 = (k ? oB[3] : oA[3]) * inv;

            const int dig = digs[b*TT + t];
            const float2 tk = tok2[dig];
            float x0 = tk.x, x1 = tk.y, x2 = pe[t];

            x0 += o0*wsm[6] + o1*wsm[9]  + o2*wsm[12] + o3*wsm[15];
            x1 += o0*wsm[7] + o1*wsm[10] + o2*wsm[13] + o3*wsm[16];
            x2 += o0*wsm[8] + o1*wsm[11] + o2*wsm[14] + o3*wsm[17];

            float r = rsqrtf((x0*x0 + x1*x1 + x2*x2) * (1.0f/3.0f) + 1e-6f);
            const float h0 = x0 * r * wsm[0];
            const float h1 = x1 * r * wsm[1];
            const float h2 = x2 * r * wsm[2];

            const float g0 = h0*wsm[18] + h1*wsm[19] + h2*wsm[20];
            const float g1 = h0*wsm[21] + h1*wsm[22] + h2*wsm[23];
            const float u0 = h0*wsm[24] + h1*wsm[25] + h2*wsm[26];
            const float u1 = h0*wsm[27] + h1*wsm[28] + h2*wsm[29];

            const float LOG2E = 1.4426950408889634f;
            const float m0 = g0 * u0 * rcpf(1.0f + ex2f(-g0 * LOG2E));
            const float m1 = g1 * u1 * rcpf(1.0f + ex2f(-g1 * LOG2E));

            x0 += m0*wsm[30] + m1*wsm[31];
            x1 += m0*wsm[32] + m1*wsm[33];
            x2 += m0*wsm[34] + m1*wsm[35];

            r = rsqrtf((x0*x0 + x1*x1 + x2*x2) * (1.0f/3.0f) + 1e-6f);
            const float f0 = x0 * r * wsm[3];
            const float f1 = x1 * r * wsm[4];

            float2* dst = (float2*)(out + ((size_t)(blockIdx.x * BPB + b) * TT + t) * VOCAB);
#pragma unroll
            for (int j = 0; j < 5; ++j) {
                const float2 ta = tok2[2*j], tb = tok2[2*j + 1];
                dst[j] = make_float2(f0*ta.x + f1*ta.y, f0*tb.x + f1*tb.y);
            }
        }
    }
}

extern "C" void kernel_launch(void* const* d_in, const int* in_sizes, int n_in,
                              void* d_out, int out_size)
{
    const int*   idx     = (const int*)  d_in[0];
    const float* arc_A   = (const float*)d_in[1];
    const float* arc_st  = (const float*)d_in[2];
    const float* arc_sd  = (const float*)d_in[3];
    const float* w_ln1   = (const float*)d_in[4];
    const float* w_ln2   = (const float*)d_in[5];
    const float* w_lnf   = (const float*)d_in[6];
    const float* w_qn    = (const float*)d_in[7];
    const float* Wq      = (const float*)d_in[8];
    const float* Wk      = (const float*)d_in[9];
    const float* Wg      = (const float*)d_in[10];
    const float* Wu      = (const float*)d_in[11];
    const float* Wd      = (const float*)d_in[12];
    float* out = (float*)d_out;

    precompute_kernel<<<VOCAB, TT>>>(arc_A, arc_st, arc_sd, w_ln1, w_qn, Wq, Wk);

    const int B = in_sizes[0] / TT;          // 16384
    const int grid = B / BPB;                // 2048 blocks, 128 threads
    adder_main<<<grid, NTH>>>(idx, w_ln2, w_lnf, Wq, Wg, Wu, Wd, out);
}

// round 10
// speedup vs baseline: 1.2467x; 1.2467x over previous
#include <cuda_runtime.h>

// R10: divergence-sorted snake pairs.
// Lane owns tokens (t1=l, t2=63-l): exactly np1+np2 = 32 pair-iters + 1 self.
// Warp j = 8 batches x 4 consecutive l in {4j..4j+3}: loop-A (dual-token)
// bound spread <=2, loop-B (token2-only) spread <=4 -> ~94% lane efficiency,
// no masked iterations, no bias constants.
// Loads: kA[b][i] etc., batch stride 132 words -> 8 distinct banks -> 1 wf.
// Table SoA with dig-stride 65 (not 64) so same-t random-dig gathers are
// conflict-free. Dynamic smem (50.4 KB).

#define TT 64
#define GB 8
#define NTH 256
#define VOCAB 10
#define KVSTR 132            // words per batch row in k/v arrays
#define TABC 656             // floats per component row (>= 10*65)

typedef unsigned long long u64;

__device__ float  g_tab[12 * TABC];     // [comp][dig*65 + t]
__device__ float2 g_tok[VOCAB];
__device__ float  g_pe[TT];

__device__ __forceinline__ float ex2f(float x) {
    float y; asm("ex2.approx.ftz.f32 %0, %1;" : "=f"(y) : "f"(x)); return y;
}
__device__ __forceinline__ float rcpf(float x) {
    float y; asm("rcp.approx.ftz.f32 %0, %1;" : "=f"(y) : "f"(x)); return y;
}
__device__ __forceinline__ u64 pack2(float lo, float hi) {
    u64 r; asm("mov.b64 %0, {%1, %2};" : "=l"(r) : "f"(lo), "f"(hi)); return r;
}
__device__ __forceinline__ void unpack2(u64 v, float& lo, float& hi) {
    asm("mov.b64 {%0, %1}, %2;" : "=f"(lo), "=f"(hi) : "l"(v));
}
__device__ __forceinline__ u64 fma2(u64 a, u64 b, u64 c) {
    u64 d; asm("fma.rn.f32x2 %0, %1, %2, %3;" : "=l"(d) : "l"(a), "l"(b), "l"(c)); return d;
}
__device__ __forceinline__ u64 mul2(u64 a, u64 b) {
    u64 d; asm("mul.rn.f32x2 %0, %1, %2;" : "=l"(d) : "l"(a), "l"(b)); return d;
}
__device__ __forceinline__ u64 add2(u64 a, u64 b) {
    u64 d; asm("add.rn.f32x2 %0, %1, %2;" : "=l"(d) : "l"(a), "l"(b)); return d;
}

// ---------------- kernel 1: 640-entry SoA table (dig-stride 65) ----------------
__global__ void precompute_kernel(
    const float* __restrict__ pA,
    const float* __restrict__ pS,
    const float* __restrict__ pD,
    const float* __restrict__ w_ln1,
    const float* __restrict__ w_qn,
    const float* __restrict__ Wq,
    const float* __restrict__ Wk)
{
    const int dig = blockIdx.x;    // 0..9
    const int t   = threadIdx.x;   // 0..63

    const float A = pA[0], ast = pS[0], astr = pD[0];
    float sa, ca;
    sincosf(ast + (float)dig * astr, &sa, &ca);
    const float x0 = A * ca;
    const float x1 = A * sa;
    const float x2 = sinf((float)t * 1.0e-4f);

    if (t == 0)   g_tok[dig] = make_float2(x0, x1);
    if (dig == 0) g_pe[t] = x2;

    const float r = rsqrtf((x0*x0 + x1*x1 + x2*x2) * (1.0f/3.0f) + 1e-6f);
    const float h0 = x0 * r * w_ln1[0];
    const float h1 = x1 * r * w_ln1[1];
    const float h2 = x2 * r * w_ln1[2];

    float qr[4], kv[4];
#pragma unroll
    for (int j = 0; j < 4; ++j) {
        qr[j] = h0 * Wq[j*3+0] + h1 * Wq[j*3+1] + h2 * Wq[j*3+2];
        kv[j] = h0 * Wk[j*3+0] + h1 * Wk[j*3+1] + h2 * Wk[j*3+2];
    }
    const float rq = rsqrtf((qr[0]*qr[0]+qr[1]*qr[1]+qr[2]*qr[2]+qr[3]*qr[3]) * 0.25f + 1e-6f);
    const float rk = rsqrtf((kv[0]*kv[0]+kv[1]*kv[1]+kv[2]*kv[2]+kv[3]*kv[3]) * 0.25f + 1e-6f);
    const float q0 = qr[0]*rq*w_qn[0], q1 = qr[1]*rq*w_qn[1];
    const float q2 = qr[2]*rq*w_qn[2], q3 = qr[3]*rq*w_qn[3];
    const float k0 = kv[0]*rk*w_qn[0], k1 = kv[1]*rk*w_qn[1];
    const float k2 = kv[2]*rk*w_qn[2], k3 = kv[3]*rk*w_qn[3];

    float s0, c0, s1, c1;
    sincosf((float)t, &s0, &c0);
    sincosf((float)t * 0.57735026918962576f, &s1, &c1);

    const float SC = 0.5f * 1.4426950408889634f;   // scale * log2(e)
    const int e = dig * 65 + t;
    g_tab[0*TABC + e] = (q0*c0 - q1*s0) * SC;
    g_tab[1*TABC + e] = (q0*s0 + q1*c0) * SC;
    g_tab[2*TABC + e] = (q2*c1 - q3*s1) * SC;
    g_tab[3*TABC + e] = (q2*s1 + q3*c1) * SC;
    g_tab[4*TABC + e] = k0*c0 - k1*s0;
    g_tab[5*TABC + e] = k0*s0 + k1*c0;
    g_tab[6*TABC + e] = k2*c1 - k3*s1;
    g_tab[7*TABC + e] = k2*s1 + k3*c1;
    g_tab[8*TABC + e]  = kv[0];
    g_tab[9*TABC + e]  = kv[1];
    g_tab[10*TABC + e] = kv[2];
    g_tab[11*TABC + e] = kv[3];
}

// wsm: [0..2] w_ln2, [3..5] w_lnf, [6..17] Wq, [18..23] Wg, [24..29] Wu, [30..35] Wd
__global__ __launch_bounds__(NTH)
void adder_main(
    const int* __restrict__ idx,
    const float* __restrict__ w_ln2,
    const float* __restrict__ w_lnf,
    const float* __restrict__ Wq,
    const float* __restrict__ Wg,
    const float* __restrict__ Wu,
    const float* __restrict__ Wd,
    float* __restrict__ out)
{
    extern __shared__ float dsm[];
    float* tab   = dsm;                         // 12*656 = 7872 floats
    float* smK01 = tab + 12 * TABC;             // GB*KVSTR each
    float* smK23 = smK01 + GB * KVSTR;
    float* smV01 = smK23 + GB * KVSTR;
    float* smV23 = smV01 + GB * KVSTR;
    int*   digs  = (int*)(smV23 + GB * KVSTR);  // 512 ints

    __shared__ float  wsm[36];
    __shared__ float2 tok2[VOCAB];
    __shared__ float  pe[TT];

    const int tid = threadIdx.x;

    if (tid < 36) {
        float v;
        if      (tid < 3)  v = w_ln2[tid];
        else if (tid < 6)  v = w_lnf[tid - 3];
        else if (tid < 18) v = Wq[tid - 6];
        else if (tid < 24) v = Wg[tid - 18];
        else if (tid < 30) v = Wu[tid - 24];
        else               v = Wd[tid - 30];
        wsm[tid] = v;
    }
    if (tid < VOCAB) tok2[tid] = g_tok[tid];
    if (tid < TT)    pe[tid]   = g_pe[tid];

    // ---- stage table (coalesced float4 copy) ----
    {
        const float4* src = (const float4*)g_tab;
        float4* dst = (float4*)tab;
#pragma unroll
        for (int i = tid; i < 12 * TABC / 4; i += NTH)
            dst[i] = src[i];
    }
    __syncthreads();

    // ---- stage k/v (2 tokens per thread; conflict-free table gathers) ----
#pragma unroll
    for (int jj = 0; jj < 2; ++jj) {
        const int tau = tid + jj * NTH;              // 0..511
        const int b = tau >> 6, t = tau & 63;
        const int dig = idx[(size_t)blockIdx.x * (GB * TT) + tau];
        digs[tau] = dig;
        const int e = dig * 65 + t;
        const int wd = b * KVSTR + 4 * (t >> 1) + (t & 1);
        smK01[wd]   = tab[4*TABC + e];
        smK01[wd+2] = tab[5*TABC + e];
        smK23[wd]   = tab[6*TABC + e];
        smK23[wd+2] = tab[7*TABC + e];
        smV01[wd]   = tab[8*TABC + e];
        smV01[wd+2] = tab[9*TABC + e];
        smV23[wd]   = tab[10*TABC + e];
        smV23[wd+2] = tab[11*TABC + e];
    }
    __syncthreads();

    // ---- attention: warp j = 8 batches x l in {4j..4j+3}; snake pair (l, 63-l) ----
    const int wj   = tid >> 5;
    const int lane = tid & 31;
    const int b    = lane & 7;
    const int dl   = lane >> 3;          // 0..3
    const int l    = 4 * wj + dl;
    const int t1   = l;
    const int t2   = 63 - l;
    const int np1  = (l + 1) >> 1;
    const int np2  = 32 - np1;

    const int dig1 = digs[b * TT + t1];
    const int dig2 = digs[b * TT + t2];
    const int e1 = dig1 * 65 + t1;
    const int e2 = dig2 * 65 + t2;

    // Q gathers: same t across 8 lanes, dig-stride 65 -> conflict-free/broadcast
    const float Q1x = tab[0*TABC+e1], Q1y = tab[1*TABC+e1];
    const float Q1z = tab[2*TABC+e1], Q1w = tab[3*TABC+e1];
    const float Q2x = tab[0*TABC+e2], Q2y = tab[1*TABC+e2];
    const float Q2z = tab[2*TABC+e2], Q2w = tab[3*TABC+e2];

    const u64 Q1xd = pack2(Q1x, Q1x), Q1yd = pack2(Q1y, Q1y);
    const u64 Q1zd = pack2(Q1z, Q1z), Q1wd = pack2(Q1w, Q1w);
    const u64 Q2xd = pack2(Q2x, Q2x), Q2yd = pack2(Q2y, Q2y);
    const u64 Q2zd = pack2(Q2z, Q2z), Q2wd = pack2(Q2w, Q2w);

    const ulonglong2* k01 = (const ulonglong2*)(smK01 + b * KVSTR);
    const ulonglong2* k23 = (const ulonglong2*)(smK23 + b * KVSTR);
    const ulonglong2* v01 = (const ulonglong2*)(smV01 + b * KVSTR);
    const ulonglong2* v23 = (const ulonglong2*)(smV23 + b * KVSTR);

    u64 s1d = 0ULL, a1x = 0ULL, a1y = 0ULL, a1z = 0ULL, a1w = 0ULL;
    u64 s2d = 0ULL, a2x = 0ULL, a2y = 0ULL, a2z = 0ULL, a2w = 0ULL;

    int i = 0;
    // loop A: both tokens active, no masks (bound spread <=2 in warp)
#pragma unroll 2
    for (; i < np1; ++i) {
        const ulonglong2 ka = k01[i], kb = k23[i];
        const ulonglong2 va = v01[i], vb = v23[i];
        const u64 sc1 = fma2(Q1xd, ka.x, fma2(Q1yd, ka.y, fma2(Q1zd, kb.x, mul2(Q1wd, kb.y))));
        const u64 sc2 = fma2(Q2xd, ka.x, fma2(Q2yd, ka.y, fma2(Q2zd, kb.x, mul2(Q2wd, kb.y))));
        float lo1, hi1, lo2, hi2;
        unpack2(sc1, lo1, hi1); unpack2(sc2, lo2, hi2);
        const u64 p1 = pack2(ex2f(lo1), ex2f(hi1));
        const u64 p2 = pack2(ex2f(lo2), ex2f(hi2));
        s1d = add2(s1d, p1); s2d = add2(s2d, p2);
        a1x = fma2(p1, va.x, a1x); a1y = fma2(p1, va.y, a1y);
        a1z = fma2(p1, vb.x, a1z); a1w = fma2(p1, vb.y, a1w);
        a2x = fma2(p2, va.x, a2x); a2y = fma2(p2, va.y, a2y);
        a2z = fma2(p2, vb.x, a2z); a2w = fma2(p2, vb.y, a2w);
    }
    // loop B: token2 only (bound spread <=4 in warp)
#pragma unroll 4
    for (; i < np2; ++i) {
        const ulonglong2 ka = k01[i], kb = k23[i];
        const ulonglong2 va = v01[i], vb = v23[i];
        const u64 sc2 = fma2(Q2xd, ka.x, fma2(Q2yd, ka.y, fma2(Q2zd, kb.x, mul2(Q2wd, kb.y))));
        float lo2, hi2;
        unpack2(sc2, lo2, hi2);
        const u64 p2 = pack2(ex2f(lo2), ex2f(hi2));
        s2d = add2(s2d, p2);
        a2x = fma2(p2, va.x, a2x); a2y = fma2(p2, va.y, a2y);
        a2z = fma2(p2, vb.x, a2z); a2w = fma2(p2, vb.y, a2w);
    }

    float lo, hi;
    unpack2(s1d, lo, hi); float sum1 = lo + hi;
    unpack2(a1x, lo, hi); float o1x = lo + hi;
    unpack2(a1y, lo, hi); float o1y = lo + hi;
    unpack2(a1z, lo, hi); float o1z = lo + hi;
    unpack2(a1w, lo, hi); float o1w = lo + hi;
    unpack2(s2d, lo, hi); float sum2 = lo + hi;
    unpack2(a2x, lo, hi); float o2x = lo + hi;
    unpack2(a2y, lo, hi); float o2y = lo + hi;
    unpack2(a2z, lo, hi); float o2z = lo + hi;
    unpack2(a2w, lo, hi); float o2w = lo + hi;

    // self term: exactly one per lane (the even token of the pair)
    {
        const int ts   = (t1 & 1) ? t2 : t1;            // even token
        const int base = b * KVSTR + 2 * ts;            // 4*(ts/2), elem 0
        const float Kx = smK01[base], Ky = smK01[base+2];
        const float Kz = smK23[base], Kw = smK23[base+2];
        const float Vx = smV01[base], Vy = smV01[base+2];
        const float Vz = smV23[base], Vw = smV23[base+2];
        if (t1 & 1) {   // self belongs to token2
            const float sc = Q2x*Kx + Q2y*Ky + Q2z*Kz + Q2w*Kw;
            const float p  = ex2f(sc);
            sum2 += p; o2x += p*Vx; o2y += p*Vy; o2z += p*Vz; o2w += p*Vw;
        } else {        // self belongs to token1
            const float sc = Q1x*Kx + Q1y*Ky + Q1z*Kz + Q1w*Kw;
            const float p  = ex2f(sc);
            sum1 += p; o1x += p*Vx; o1y += p*Vy; o1z += p*Vz; o1w += p*Vw;
        }
    }

    // ---- epilogue: 2 tokens per lane, direct gmem stores ----
#pragma unroll
    for (int which = 0; which < 2; ++which) {
        const int t   = which ? t2 : t1;
        const int dig = which ? dig2 : dig1;
        const float sm = which ? sum2 : sum1;
        const float inv = rcpf(sm);
        const float o0 = (which ? o2x : o1x) * inv;
        const float o1 = (which ? o2y : o1y) * inv;
        const float o2 = (which ? o2z : o1z) * inv;
        const float o3 = (which ? o2w : o1w) * inv;

        const float2 tk = tok2[dig];
        float x0 = tk.x, x1 = tk.y, x2 = pe[t];

        x0 += o0*wsm[6] + o1*wsm[9]  + o2*wsm[12] + o3*wsm[15];
        x1 += o0*wsm[7] + o1*wsm[10] + o2*wsm[13] + o3*wsm[16];
        x2 += o0*wsm[8] + o1*wsm[11] + o2*wsm[14] + o3*wsm[17];

        float r = rsqrtf((x0*x0 + x1*x1 + x2*x2) * (1.0f/3.0f) + 1e-6f);
        const float h0 = x0 * r * wsm[0];
        const float h1 = x1 * r * wsm[1];
        const float h2 = x2 * r * wsm[2];

        const float g0 = h0*wsm[18] + h1*wsm[19] + h2*wsm[20];
        const float g1 = h0*wsm[21] + h1*wsm[22] + h2*wsm[23];
        const float u0 = h0*wsm[24] + h1*wsm[25] + h2*wsm[26];
        const float u1 = h0*wsm[27] + h1*wsm[28] + h2*wsm[29];

        const float LOG2E = 1.4426950408889634f;
        const float m0 = g0 * u0 * rcpf(1.0f + ex2f(-g0 * LOG2E));
        const float m1 = g1 * u1 * rcpf(1.0f + ex2f(-g1 * LOG2E));

        x0 += m0*wsm[30] + m1*wsm[31];
        x1 += m0*wsm[32] + m1*wsm[33];
        x2 += m0*wsm[34] + m1*wsm[35];

        r = rsqrtf((x0*x0 + x1*x1 + x2*x2) * (1.0f/3.0f) + 1e-6f);
        const float f0 = x0 * r * wsm[3];
        const float f1 = x1 * r * wsm[4];

        float2* dst = (float2*)(out + ((size_t)(blockIdx.x * GB + b) * TT + t) * VOCAB);
#pragma unroll
        for (int j = 0; j < 5; ++j) {
            const float2 ta = tok2[2*j], tb = tok2[2*j + 1];
            dst[j] = make_float2(f0*ta.x + f1*ta.y, f0*tb.x + f1*tb.y);
        }
    }
}

extern "C" void kernel_launch(void* const* d_in, const int* in_sizes, int n_in,
                              void* d_out, int out_size)
{
    const int*   idx     = (const int*)  d_in[0];
    const float* arc_A   = (const float*)d_in[1];
    const float* arc_st  = (const float*)d_in[2];
    const float* arc_sd  = (const float*)d_in[3];
    const float* w_ln1   = (const float*)d_in[4];
    const float* w_ln2   = (const float*)d_in[5];
    const float* w_lnf   = (const float*)d_in[6];
    const float* w_qn    = (const float*)d_in[7];
    const float* Wq      = (const float*)d_in[8];
    const float* Wk      = (const float*)d_in[9];
    const float* Wg      = (const float*)d_in[10];
    const float* Wu      = (const float*)d_in[11];
    const float* Wd      = (const float*)d_in[12];
    float* out = (float*)d_out;

    const int smem_bytes = (12 * TABC + 4 * GB * KVSTR) * 4 + GB * TT * 4;
    cudaFuncSetAttribute(adder_main, cudaFuncAttributeMaxDynamicSharedMemorySize,
                         smem_bytes);

    precompute_kernel<<<VOCAB, TT>>>(arc_A, arc_st, arc_sd, w_ln1, w_qn, Wq, Wk);

    const int B = in_sizes[0] / TT;          // 16384
    const int grid = B / GB;                 // 2048 blocks
    adder_main<<<grid, NTH, smem_bytes>>>(idx, w_ln2, w_lnf, Wq, Wg, Wu, Wd, out);
}